// round 10
// baseline (speedup 1.0000x reference)
#include <cuda_runtime.h>
#include <math.h>

#define B 4
#define H 16
#define T 8192
#define D 64
#define C 64
#define W 128
#define NC 64
#define BH (B*H)

// ---------------- scratch (static device globals; no runtime alloc) ----------------
__device__ float g_knorm[(size_t)B*H*T*D];   // 134 MB
__device__ float g_dists[(size_t)B*H*C*T];   // 134 MB, layout (b,h,c,t)
__device__ int   g_buckets[B*H*T];
__device__ float g_part[(size_t)B*H*C*D];    // per-b partial sums, layout ((b,h,c),d)
__device__ int   g_bins[H*C];
__device__ float g_meansu[H*C*D];
__device__ int   g_indices[B*H*T];
__device__ int   g_count[B*H*T];

// ---------------- K0: zero accumulators ----------------
__global__ void k_zero(float* __restrict__ out) {
    size_t i = (size_t)blockIdx.x * blockDim.x + threadIdx.x;
    size_t stride = (size_t)gridDim.x * blockDim.x;
    const size_t NOUT = (size_t)B*H*T*D;
    for (size_t p = i; p < NOUT; p += stride) out[p] = 0.f;
    for (size_t p = i; p < (size_t)B*H*T; p += stride) g_count[p] = 0;
    for (size_t p = i; p < (size_t)H*C; p += stride) g_bins[p] = 0;
}

// ---------------- K1: k_norm = l2norm(qk), bit-exact (sequential FUSED fma ssq chain) ----------------
__global__ void k_norm(const float* __restrict__ qk) {
    int tok = blockIdx.x * blockDim.x + threadIdx.x;
    if (tok >= B*H*T) return;
    const float4* src = (const float4*)(qk + (size_t)tok * D);
    float v[64];
    #pragma unroll
    for (int i = 0; i < 16; i++) {
        float4 q = src[i];
        v[4*i+0] = q.x; v[4*i+1] = q.y; v[4*i+2] = q.z; v[4*i+3] = q.w;
    }
    float s = 0.f;
    #pragma unroll
    for (int d = 0; d < 64; d++) s = __fmaf_rn(v[d], v[d], s);
    float n = fmaxf(__fsqrt_rn(s), 1e-12f);
    float4* dst = (float4*)(g_knorm + (size_t)tok * D);
    #pragma unroll
    for (int i = 0; i < 16; i++) {
        float4 o;
        o.x = __fdiv_rn(v[4*i+0], n);
        o.y = __fdiv_rn(v[4*i+1], n);
        o.z = __fdiv_rn(v[4*i+2], n);
        o.w = __fdiv_rn(v[4*i+3], n);
        dst[i] = o;
    }
}

// ---------------- K2: buckets = argmax_c (k_norm . means) ----------------
// 256 threads; 4 tokens x 4 clusters register tile on transposed [d][x] smem.
// Per-output chain: sequential ascending-d fma (bit-identical to before).
__global__ void k_buckets(const float* __restrict__ means) {
    __shared__ float sM[64*68];   // [d][c], pitch 68 (16B-aligned rows, spread banks)
    __shared__ float sT[64*68];   // [d][tok]
    int blk = blockIdx.x;
    int bh = blk / (T/64);
    int chunk = blk % (T/64);
    int h = bh % H;
    int tid = threadIdx.x;

    for (int i = tid; i < C*D; i += 256) {
        int c = i >> 6, d = i & 63;
        sM[d*68 + c] = means[(size_t)h*C*D + i];
    }
    size_t base = ((size_t)bh*T + (size_t)chunk*64) * D;
    for (int i = tid; i < 64*D; i += 256) {
        int r = i >> 6, d = i & 63;
        sT[d*68 + r] = g_knorm[base + i];
    }
    __syncthreads();

    int tx = tid & 15, ty = tid >> 4;       // tx -> cluster group, ty -> token group
    int tok0 = ty*4, c0 = tx*4;
    float a[4][4];
    #pragma unroll
    for (int r = 0; r < 4; r++)
        #pragma unroll
        for (int cc = 0; cc < 4; cc++) a[r][cc] = 0.f;

    #pragma unroll 8
    for (int d = 0; d < 64; d++) {
        float4 q4 = *(const float4*)&sT[d*68 + tok0];
        float4 m4 = *(const float4*)&sM[d*68 + c0];
        float qv[4] = {q4.x, q4.y, q4.z, q4.w};
        float mv[4] = {m4.x, m4.y, m4.z, m4.w};
        #pragma unroll
        for (int r = 0; r < 4; r++)
            #pragma unroll
            for (int cc = 0; cc < 4; cc++)
                a[r][cc] = __fmaf_rn(qv[r], mv[cc], a[r][cc]);
    }
    __syncthreads();

    float* sSim = sM;   // alias: 4096 floats needed, sM holds 4352
    #pragma unroll
    for (int r = 0; r < 4; r++)
        #pragma unroll
        for (int cc = 0; cc < 4; cc++)
            sSim[(tok0 + r)*64 + c0 + cc] = a[r][cc];
    __syncthreads();

    if (tid < 64) {
        float best = -1e30f; int bi = 0;
        #pragma unroll 8
        for (int c = 0; c < C; c++) {
            float s = sSim[tid*64 + c];
            if (s > best) { best = s; bi = c; }   // strict > : first index on ties
        }
        g_buckets[(size_t)bh*T + chunk*64 + tid] = bi;
    }
}

// ---------------- K3: per-(b,h) single-pass cluster sums, STRICT t-ascending ----------------
// one warp per (b,h); smem accumulator per cluster. Each lane owns dims 2L,2L+1;
// per-cluster additions occur in strict ascending-t program order (bit-identical).
__global__ void k_sumsB() {
    __shared__ float acc[C*D];    // 16 KB
    __shared__ int cnt[C];
    int bh = blockIdx.x;          // b*H + h
    int lane = threadIdx.x;       // 32 threads
    for (int i = lane; i < (C*D)/2; i += 32) ((float2*)acc)[i] = make_float2(0.f, 0.f);
    for (int i = lane; i < C; i += 32) cnt[i] = 0;
    __syncwarp();
    size_t base = (size_t)bh * T;
    const int* bkt = g_buckets + base;
    #pragma unroll 4
    for (int t = 0; t < T; t++) {
        int bk = __ldg(&bkt[t]);
        float2 xv = ((const float2*)(g_knorm + (base + t) * D))[lane];
        float2* a = (float2*)&acc[bk*D + 2*lane];
        float2 cur = *a;
        cur.x = __fadd_rn(cur.x, xv.x);
        cur.y = __fadd_rn(cur.y, xv.y);
        *a = cur;
        if (lane == 0) cnt[bk]++;
    }
    __syncwarp();
    for (int c = 0; c < C; c++)
        ((float2*)(g_part + ((size_t)bh*C + c) * D))[lane] = ((float2*)&acc[c*D])[lane];
    int h = bh & (H-1);
    for (int c = lane; c < C; c += 32) atomicAdd(&g_bins[h*C + c], cnt[c]);
}

// ---------------- K4: means_upd: b-ascending combine + FUSED sequential ssq + division ----------------
__global__ void k_meansupd(const float* __restrict__ means) {
    int inst = blockIdx.x * blockDim.x + threadIdx.x;   // h*C + c
    if (inst >= H*C) return;
    float sv[64];
    #pragma unroll 4
    for (int d = 0; d < D; d++) {
        float s = g_part[((size_t)0*1024 + inst)*D + d];
        s = __fadd_rn(s, g_part[((size_t)1*1024 + inst)*D + d]);
        s = __fadd_rn(s, g_part[((size_t)2*1024 + inst)*D + d]);
        s = __fadd_rn(s, g_part[((size_t)3*1024 + inst)*D + d]);
        sv[d] = s;
    }
    float ssq = 0.f;
    #pragma unroll
    for (int d = 0; d < D; d++) ssq = __fmaf_rn(sv[d], sv[d], ssq);
    float n = fmaxf(__fsqrt_rn(ssq), 1e-12f);
    bool empty = (g_bins[inst] == 0);
    #pragma unroll 4
    for (int d = 0; d < D; d++) {
        float o = empty ? means[(size_t)inst*D + d] : __fdiv_rn(sv[d], n);
        g_meansu[(size_t)inst*D + d] = o;
    }
}

// ---------------- K5: dists (b,h,c,t) = k_norm . means_upd^T ----------------
// same 4x4 register tiling; chain per output identical (ascending-d fma).
__global__ void k_dists() {
    __shared__ float sM[64*68];
    __shared__ float sT[64*68];
    int blk = blockIdx.x;
    int bh = blk / (T/64);
    int chunk = blk % (T/64);
    int h = bh % H;
    int tid = threadIdx.x;

    for (int i = tid; i < C*D; i += 256) {
        int c = i >> 6, d = i & 63;
        sM[d*68 + c] = g_meansu[(size_t)h*C*D + i];
    }
    size_t base = ((size_t)bh*T + (size_t)chunk*64) * D;
    for (int i = tid; i < 64*D; i += 256) {
        int r = i >> 6, d = i & 63;
        sT[d*68 + r] = g_knorm[base + i];
    }
    __syncthreads();

    int tx = tid & 15, ty = tid >> 4;
    int tok0 = ty*4, c0 = tx*4;
    float a[4][4];
    #pragma unroll
    for (int r = 0; r < 4; r++)
        #pragma unroll
        for (int cc = 0; cc < 4; cc++) a[r][cc] = 0.f;

    #pragma unroll 8
    for (int d = 0; d < 64; d++) {
        float4 q4 = *(const float4*)&sT[d*68 + tok0];
        float4 m4 = *(const float4*)&sM[d*68 + c0];
        float qv[4] = {q4.x, q4.y, q4.z, q4.w};
        float mv[4] = {m4.x, m4.y, m4.z, m4.w};
        #pragma unroll
        for (int r = 0; r < 4; r++)
            #pragma unroll
            for (int cc = 0; cc < 4; cc++)
                a[r][cc] = __fmaf_rn(qv[r], mv[cc], a[r][cc]);
    }
    __syncthreads();

    float* sSim = sM;    // alias: [c][tok] for coalesced store
    #pragma unroll
    for (int r = 0; r < 4; r++)
        #pragma unroll
        for (int cc = 0; cc < 4; cc++)
            sSim[(c0 + cc)*64 + tok0 + r] = a[r][cc];
    __syncthreads();

    for (int i = tid; i < C*64; i += 256) {
        int c = i >> 6, t = i & 63;
        g_dists[((size_t)bh*C + c)*T + (size_t)chunk*64 + t] = sSim[i];
    }
}

// ---------------- K6: top-128 per (b,h,c): radix select + bitonic index sort ----------------
__global__ void k_topk() {
    __shared__ unsigned int keys[T];        // 32 KB
    __shared__ unsigned int hist[256];
    __shared__ unsigned int sh_pref;
    __shared__ int sh_k;
    __shared__ int outbuf[W];
    __shared__ int gtc;
    __shared__ int eqbase;
    __shared__ int warpTot[8];

    int inst = blockIdx.x;                  // (b*H+h)*C + c
    int bh = inst / C;
    int c = inst % C;
    int tid = threadIdx.x, lane = tid & 31, wid = tid >> 5;

    const float* row = g_dists + (size_t)inst * T;
    for (int i = tid; i < T; i += 256) {
        unsigned int u = __float_as_uint(row[i]);
        keys[i] = (u & 0x80000000u) ? ~u : (u | 0x80000000u);  // monotone float->uint
    }
    __syncthreads();

    unsigned int prefix = 0; int k = 128;
    for (int sh = 24; sh >= 0; sh -= 8) {
        hist[tid] = 0;
        __syncthreads();
        unsigned int hmask = (sh == 24) ? 0u : (0xFFFFFFFFu << (sh + 8));
        for (int i = tid; i < T; i += 256) {
            unsigned int kk = keys[i];
            if ((kk & hmask) == prefix) atomicAdd(&hist[(kk >> sh) & 255], 1u);
        }
        __syncthreads();
        if (tid == 0) {
            int cum = 0;
            for (int bkt = 255; bkt >= 0; bkt--) {
                cum += (int)hist[bkt];
                if (cum >= k) {
                    sh_pref = prefix | ((unsigned int)bkt << sh);
                    sh_k = k - (cum - (int)hist[bkt]);
                    break;
                }
            }
        }
        __syncthreads();
        prefix = sh_pref; k = sh_k;
        __syncthreads();
    }
    unsigned int Tkey = prefix;
    int k_rem = k;
    int count_gt = 128 - k_rem;

    if (tid == 0) { gtc = 0; eqbase = 0; }
    __syncthreads();

    for (int i = tid; i < T; i += 256) {
        if (keys[i] > Tkey) {
            int p = atomicAdd(&gtc, 1);
            outbuf[p] = i;
        }
    }
    __syncthreads();

    for (int ch = 0; ch < T; ch += 256) {
        int i = ch + tid;
        bool eq = (keys[i] == Tkey);
        unsigned int bal = __ballot_sync(0xffffffffu, eq);
        int wpre = __popc(bal & ((1u << lane) - 1u));
        if (lane == 0) warpTot[wid] = __popc(bal);
        __syncthreads();
        int base = eqbase;
        int woff = 0;
        for (int w = 0; w < wid; w++) woff += warpTot[w];
        if (eq) {
            int rank = base + woff + wpre;
            if (rank < k_rem) outbuf[count_gt + rank] = i;
        }
        __syncthreads();
        if (tid == 0) {
            int tot = 0;
            for (int w = 0; w < 8; w++) tot += warpTot[w];
            eqbase += tot;
        }
        __syncthreads();
        if (eqbase >= k_rem) break;
    }

    for (int size = 2; size <= 128; size <<= 1) {
        for (int stride = size >> 1; stride > 0; stride >>= 1) {
            __syncthreads();
            if (tid < 128) {
                int partner = tid ^ stride;
                if (partner > tid) {
                    bool up = ((tid & size) == 0);
                    int a = outbuf[tid], b2 = outbuf[partner];
                    if ((a > b2) == up) { outbuf[tid] = b2; outbuf[partner] = a; }
                }
            }
        }
    }
    __syncthreads();
    if (tid < 128) g_indices[(size_t)bh*T + c*W + tid] = outbuf[tid];
}

// ---------------- K7: windowed attention + scatter (4-row register blocking) ----------------
// sK / sR pitch 66 (even -> float2-aligned rows), sQ / sV pitch 64.
#define ATTN_SMEM ((128*64 + 128*66 + 128*64 + 128*66) * 4 + 128 * 4)

__global__ __launch_bounds__(256, 1)
void k_attn(const float* __restrict__ qk, const float* __restrict__ v,
            const float* __restrict__ rw, float* __restrict__ out) {
    extern __shared__ float sm[];
    float* sQ = sm;                      // [128][64]
    float* sK = sQ + 128*64;             // [128][66]
    float* sV = sK + 128*66;             // [128][64]
    float* sR = sV + 128*64;             // [128][66]
    int*   sIdx = (int*)(sR + 128*66);

    int inst = blockIdx.x;
    int bh = inst / NC;
    int n  = inst % NC;
    int h  = bh % H;
    int tid = threadIdx.x, lane = tid & 31, wid = tid >> 5;

    if (tid < 128) sIdx[tid] = g_indices[(size_t)bh*T + n*W + tid];
    __syncthreads();

    for (int r = wid; r < 128; r += 8) {
        int g = sIdx[r];
        size_t off = ((size_t)bh*T + g) * D;
        float2 a = ((const float2*)(qk + off))[lane];
        float2 b2 = ((const float2*)(g_knorm + off))[lane];
        float2 c2 = ((const float2*)(v + off))[lane];
        sQ[r*64 + 2*lane] = a.x;  sQ[r*64 + 2*lane + 1] = a.y;
        sK[r*66 + 2*lane] = b2.x; sK[r*66 + 2*lane + 1] = b2.y;
        sV[r*64 + 2*lane] = c2.x; sV[r*64 + 2*lane + 1] = c2.y;
        float2 rr = ((const float2*)(rw + ((size_t)r*H + h)*D))[lane];
        sR[r*66 + 2*lane] = rr.x; sR[r*66 + 2*lane + 1] = rr.y;
    }
    __syncthreads();

    const float scale = 0.125f;

    for (int p = 0; p < 4; p++) {
        int irow[4];
        #pragma unroll
        for (int q = 0; q < 4; q++) irow[q] = wid + 8*q + 32*p;

        float a[4][4];
        #pragma unroll
        for (int q = 0; q < 4; q++)
            #pragma unroll
            for (int jj = 0; jj < 4; jj++) a[q][jj] = 0.f;

        // dots = q . kk  (float2 over d, 4 rows x 4 j-cols)
        #pragma unroll 4
        for (int d2 = 0; d2 < 32; d2++) {
            float2 qv[4];
            #pragma unroll
            for (int q = 0; q < 4; q++) qv[q] = *(const float2*)&sQ[irow[q]*64 + 2*d2];
            #pragma unroll
            for (int jj = 0; jj < 4; jj++) {
                float2 kv = *(const float2*)&sK[(lane + 32*jj)*66 + 2*d2];
                #pragma unroll
                for (int q = 0; q < 4; q++)
                    a[q][jj] += qv[q].x*kv.x + qv[q].y*kv.y;
            }
        }

        // rel: for j < i, += q_i . rw[127 + j - i]
        #pragma unroll
        for (int q = 0; q < 4; q++) {
            int i = irow[q];
            #pragma unroll
            for (int jj = 0; jj < 4; jj++) {
                int j = lane + 32*jj;
                if (j < i) {
                    int r = 127 + j - i;
                    float s = 0.f;
                    for (int d2 = 0; d2 < 32; d2++) {
                        float2 qq = *(const float2*)&sQ[i*64 + 2*d2];
                        float2 rr = *(const float2*)&sR[r*66 + 2*d2];
                        s += qq.x*rr.x + qq.y*rr.y;
                    }
                    a[q][jj] += s;
                }
            }
        }

        // softmax per row
        float pr[4][4];
        #pragma unroll
        for (int q = 0; q < 4; q++) {
            int i = irow[q];
            float m = -1e30f;
            #pragma unroll
            for (int jj = 0; jj < 4; jj++) {
                int j = lane + 32*jj;
                a[q][jj] = (j == i) ? -50000.0f : a[q][jj]*scale;
                m = fmaxf(m, a[q][jj]);
            }
            #pragma unroll
            for (int o = 16; o; o >>= 1) m = fmaxf(m, __shfl_xor_sync(0xffffffffu, m, o));
            float s = 0.f;
            #pragma unroll
            for (int jj = 0; jj < 4; jj++) { pr[q][jj] = expf(a[q][jj] - m); s += pr[q][jj]; }
            #pragma unroll
            for (int o = 16; o; o >>= 1) s += __shfl_xor_sync(0xffffffffu, s, o);
            float inv = 1.0f / s;
            #pragma unroll
            for (int jj = 0; jj < 4; jj++) pr[q][jj] *= inv;
        }

        // bo = attn @ v  (lane owns dims 2*lane, 2*lane+1)
        float ox[4], oy[4];
        #pragma unroll
        for (int q = 0; q < 4; q++) { ox[q] = 0.f; oy[q] = 0.f; }
        #pragma unroll
        for (int jj = 0; jj < 4; jj++) {
            for (int js = 0; js < 32; js++) {
                float2 vv = ((const float2*)(sV + (jj*32 + js)*64))[lane];
                #pragma unroll
                for (int q = 0; q < 4; q++) {
                    float w = __shfl_sync(0xffffffffu, pr[q][jj], js);
                    ox[q] += w * vv.x;
                    oy[q] += w * vv.y;
                }
            }
        }

        // scatter
        #pragma unroll
        for (int q = 0; q < 4; q++) {
            int g = sIdx[irow[q]];
            float* dst = out + ((size_t)bh*T + g)*D + 2*lane;
            atomicAdd(dst,     ox[q]);
            atomicAdd(dst + 1, oy[q]);
            if (lane == 0) atomicAdd(&g_count[(size_t)bh*T + g], 1);
        }
    }
}

// ---------------- K8: finalize out /= (count + 1e-5) ----------------
__global__ void k_final(float* __restrict__ out) {
    size_t i = (size_t)blockIdx.x * blockDim.x + threadIdx.x;
    size_t stride = (size_t)gridDim.x * blockDim.x;
    const size_t N = (size_t)B*H*T*D;
    for (size_t p = i; p < N; p += stride) {
        float cnt = (float)g_count[p >> 6];
        out[p] = out[p] / (cnt + 1e-5f);
    }
}

// ---------------- launch ----------------
extern "C" void kernel_launch(void* const* d_in, const int* in_sizes, int n_in,
                              void* d_out, int out_size) {
    const float* qk    = (const float*)d_in[0];
    const float* v     = (const float*)d_in[1];
    const float* means = (const float*)d_in[2];
    const float* rw    = (const float*)d_in[3];
    float* out = (float*)d_out;

    cudaFuncSetAttribute(k_attn, cudaFuncAttributeMaxDynamicSharedMemorySize, ATTN_SMEM);

    k_zero<<<2048, 256>>>(out);
    k_norm<<<(B*H*T + 255)/256, 256>>>(qk);
    k_buckets<<<BH*(T/64), 256>>>(means);
    k_sumsB<<<BH, 32>>>();
    k_meansupd<<<(H*C + 255)/256, 256>>>(means);
    k_dists<<<BH*(T/64), 256>>>();
    k_topk<<<BH*C, 256>>>();
    k_attn<<<BH*NC, 256, ATTN_SMEM>>>(qk, v, rw, out);
    k_final<<<4096, 256>>>(out);
}

// round 11
// speedup vs baseline: 1.3988x; 1.3988x over previous
#include <cuda_runtime.h>
#include <math.h>

#define B 4
#define H 16
#define T 8192
#define D 64
#define C 64
#define W 128
#define NC 64
#define BH (B*H)

// ---------------- scratch (static device globals; no runtime alloc) ----------------
__device__ float g_knorm[(size_t)B*H*T*D];   // 134 MB
__device__ float g_dists[(size_t)B*H*C*T];   // 134 MB, layout (b,h,c,t)
__device__ int   g_buckets[B*H*T];
__device__ float g_part[(size_t)B*H*C*D];    // per-b partial sums, layout ((b,h,c),d)
__device__ int   g_bins[H*C];
__device__ float g_meansu[H*C*D];
__device__ int   g_indices[B*H*T];
__device__ int   g_count[B*H*T];

// ---------------- K0: zero accumulators ----------------
__global__ void k_zero(float* __restrict__ out) {
    size_t i = (size_t)blockIdx.x * blockDim.x + threadIdx.x;
    size_t stride = (size_t)gridDim.x * blockDim.x;
    const size_t NOUT = (size_t)B*H*T*D;
    for (size_t p = i; p < NOUT; p += stride) out[p] = 0.f;
    for (size_t p = i; p < (size_t)B*H*T; p += stride) g_count[p] = 0;
    for (size_t p = i; p < (size_t)H*C; p += stride) g_bins[p] = 0;
}

// ---------------- K1: k_norm = l2norm(qk), bit-exact (sequential FUSED fma ssq chain) ----------------
__global__ void k_norm(const float* __restrict__ qk) {
    int tok = blockIdx.x * blockDim.x + threadIdx.x;
    if (tok >= B*H*T) return;
    const float4* src = (const float4*)(qk + (size_t)tok * D);
    float v[64];
    #pragma unroll
    for (int i = 0; i < 16; i++) {
        float4 q = src[i];
        v[4*i+0] = q.x; v[4*i+1] = q.y; v[4*i+2] = q.z; v[4*i+3] = q.w;
    }
    float s = 0.f;
    #pragma unroll
    for (int d = 0; d < 64; d++) s = __fmaf_rn(v[d], v[d], s);
    float n = fmaxf(__fsqrt_rn(s), 1e-12f);
    float4* dst = (float4*)(g_knorm + (size_t)tok * D);
    #pragma unroll
    for (int i = 0; i < 16; i++) {
        float4 o;
        o.x = __fdiv_rn(v[4*i+0], n);
        o.y = __fdiv_rn(v[4*i+1], n);
        o.z = __fdiv_rn(v[4*i+2], n);
        o.w = __fdiv_rn(v[4*i+3], n);
        dst[i] = o;
    }
}

// ---------------- K2: buckets = argmax_c (k_norm . means) ----------------
// 256 threads; 4 tokens x 4 clusters register tile on transposed [d][x] smem.
__global__ void k_buckets(const float* __restrict__ means) {
    __shared__ float sM[64*68];   // [d][c]
    __shared__ float sT[64*68];   // [d][tok]
    int blk = blockIdx.x;
    int bh = blk / (T/64);
    int chunk = blk % (T/64);
    int h = bh % H;
    int tid = threadIdx.x;

    for (int i = tid; i < C*D; i += 256) {
        int c = i >> 6, d = i & 63;
        sM[d*68 + c] = means[(size_t)h*C*D + i];
    }
    size_t base = ((size_t)bh*T + (size_t)chunk*64) * D;
    for (int i = tid; i < 64*D; i += 256) {
        int r = i >> 6, d = i & 63;
        sT[d*68 + r] = g_knorm[base + i];
    }
    __syncthreads();

    int tx = tid & 15, ty = tid >> 4;
    int tok0 = ty*4, c0 = tx*4;
    float a[4][4];
    #pragma unroll
    for (int r = 0; r < 4; r++)
        #pragma unroll
        for (int cc = 0; cc < 4; cc++) a[r][cc] = 0.f;

    #pragma unroll 8
    for (int d = 0; d < 64; d++) {
        float4 q4 = *(const float4*)&sT[d*68 + tok0];
        float4 m4 = *(const float4*)&sM[d*68 + c0];
        float qv[4] = {q4.x, q4.y, q4.z, q4.w};
        float mv[4] = {m4.x, m4.y, m4.z, m4.w};
        #pragma unroll
        for (int r = 0; r < 4; r++)
            #pragma unroll
            for (int cc = 0; cc < 4; cc++)
                a[r][cc] = __fmaf_rn(qv[r], mv[cc], a[r][cc]);
    }
    __syncthreads();

    float* sSim = sM;
    #pragma unroll
    for (int r = 0; r < 4; r++)
        #pragma unroll
        for (int cc = 0; cc < 4; cc++)
            sSim[(tok0 + r)*64 + c0 + cc] = a[r][cc];
    __syncthreads();

    if (tid < 64) {
        float best = -1e30f; int bi = 0;
        #pragma unroll 8
        for (int c = 0; c < C; c++) {
            float s = sSim[tid*64 + c];
            if (s > best) { best = s; bi = c; }   // strict > : first index on ties
        }
        g_buckets[(size_t)bh*T + chunk*64 + tid] = bi;
    }
}

// ---------------- K3: cluster sums — smem-staged buckets, warp-per-cluster ----------------
// 2 blocks x 1024 threads per (b,h); buckets staged ONCE to smem; warp w owns
// cluster c = half*32 + w; scans smem bucket list (broadcast), loads knorm row
// only on match. Additions per cluster: single strict t-ascending chain
// (bit-identical to reference scatter order). ~4096 warps chip-wide.
__global__ __launch_bounds__(1024, 1) void k_sumsC() {
    __shared__ int sb[T];                 // 32 KB
    int bh = blockIdx.x >> 1;
    int half = blockIdx.x & 1;
    int tid = threadIdx.x;
    int lane = tid & 31, wid = tid >> 5;
    size_t base = (size_t)bh * T;
    for (int i = tid; i < T/4; i += 1024)
        ((int4*)sb)[i] = ((const int4*)(g_buckets + base))[i];
    __syncthreads();

    int c = half*32 + wid;
    float ax = 0.f, ay = 0.f;
    int cnt = 0;
    for (int t = 0; t < T; t += 4) {
        int4 bk = *(const int4*)&sb[t];   // LDS broadcast across lanes
        if (bk.x == c) { float2 xv = ((const float2*)(g_knorm + (base + t + 0)*D))[lane];
                         ax = __fadd_rn(ax, xv.x); ay = __fadd_rn(ay, xv.y); cnt++; }
        if (bk.y == c) { float2 xv = ((const float2*)(g_knorm + (base + t + 1)*D))[lane];
                         ax = __fadd_rn(ax, xv.x); ay = __fadd_rn(ay, xv.y); cnt++; }
        if (bk.z == c) { float2 xv = ((const float2*)(g_knorm + (base + t + 2)*D))[lane];
                         ax = __fadd_rn(ax, xv.x); ay = __fadd_rn(ay, xv.y); cnt++; }
        if (bk.w == c) { float2 xv = ((const float2*)(g_knorm + (base + t + 3)*D))[lane];
                         ax = __fadd_rn(ax, xv.x); ay = __fadd_rn(ay, xv.y); cnt++; }
    }
    float2 o; o.x = ax; o.y = ay;
    ((float2*)(g_part + ((size_t)bh*C + c) * D))[lane] = o;
    if (lane == 0) atomicAdd(&g_bins[(bh & (H-1))*C + c], cnt);
}

// ---------------- K4: means_upd: b-ascending combine + FUSED sequential ssq + division ----------------
__global__ void k_meansupd(const float* __restrict__ means) {
    int inst = blockIdx.x * blockDim.x + threadIdx.x;   // h*C + c
    if (inst >= H*C) return;
    float sv[64];
    #pragma unroll 4
    for (int d = 0; d < D; d++) {
        float s = g_part[((size_t)0*1024 + inst)*D + d];
        s = __fadd_rn(s, g_part[((size_t)1*1024 + inst)*D + d]);
        s = __fadd_rn(s, g_part[((size_t)2*1024 + inst)*D + d]);
        s = __fadd_rn(s, g_part[((size_t)3*1024 + inst)*D + d]);
        sv[d] = s;
    }
    float ssq = 0.f;
    #pragma unroll
    for (int d = 0; d < D; d++) ssq = __fmaf_rn(sv[d], sv[d], ssq);
    float n = fmaxf(__fsqrt_rn(ssq), 1e-12f);
    bool empty = (g_bins[inst] == 0);
    #pragma unroll 4
    for (int d = 0; d < D; d++) {
        float o = empty ? means[(size_t)inst*D + d] : __fdiv_rn(sv[d], n);
        g_meansu[(size_t)inst*D + d] = o;
    }
}

// ---------------- K5: dists (b,h,c,t) = k_norm . means_upd^T ----------------
__global__ void k_dists() {
    __shared__ float sM[64*68];
    __shared__ float sT[64*68];
    int blk = blockIdx.x;
    int bh = blk / (T/64);
    int chunk = blk % (T/64);
    int h = bh % H;
    int tid = threadIdx.x;

    for (int i = tid; i < C*D; i += 256) {
        int c = i >> 6, d = i & 63;
        sM[d*68 + c] = g_meansu[(size_t)h*C*D + i];
    }
    size_t base = ((size_t)bh*T + (size_t)chunk*64) * D;
    for (int i = tid; i < 64*D; i += 256) {
        int r = i >> 6, d = i & 63;
        sT[d*68 + r] = g_knorm[base + i];
    }
    __syncthreads();

    int tx = tid & 15, ty = tid >> 4;
    int tok0 = ty*4, c0 = tx*4;
    float a[4][4];
    #pragma unroll
    for (int r = 0; r < 4; r++)
        #pragma unroll
        for (int cc = 0; cc < 4; cc++) a[r][cc] = 0.f;

    #pragma unroll 8
    for (int d = 0; d < 64; d++) {
        float4 q4 = *(const float4*)&sT[d*68 + tok0];
        float4 m4 = *(const float4*)&sM[d*68 + c0];
        float qv[4] = {q4.x, q4.y, q4.z, q4.w};
        float mv[4] = {m4.x, m4.y, m4.z, m4.w};
        #pragma unroll
        for (int r = 0; r < 4; r++)
            #pragma unroll
            for (int cc = 0; cc < 4; cc++)
                a[r][cc] = __fmaf_rn(qv[r], mv[cc], a[r][cc]);
    }
    __syncthreads();

    float* sSim = sM;    // alias: [c][tok] for coalesced store
    #pragma unroll
    for (int r = 0; r < 4; r++)
        #pragma unroll
        for (int cc = 0; cc < 4; cc++)
            sSim[(c0 + cc)*64 + tok0 + r] = a[r][cc];
    __syncthreads();

    for (int i = tid; i < C*64; i += 256) {
        int c = i >> 6, t = i & 63;
        g_dists[((size_t)bh*C + c)*T + (size_t)chunk*64 + t] = sSim[i];
    }
}

// ---------------- K6: top-128 per (b,h,c): radix select + bitonic index sort ----------------
__global__ void k_topk() {
    __shared__ unsigned int keys[T];        // 32 KB
    __shared__ unsigned int hist[256];
    __shared__ unsigned int sh_pref;
    __shared__ int sh_k;
    __shared__ int outbuf[W];
    __shared__ int gtc;
    __shared__ int eqbase;
    __shared__ int warpTot[8];

    int inst = blockIdx.x;                  // (b*H+h)*C + c
    int bh = inst / C;
    int c = inst % C;
    int tid = threadIdx.x, lane = tid & 31, wid = tid >> 5;

    const float* row = g_dists + (size_t)inst * T;
    for (int i = tid; i < T; i += 256) {
        unsigned int u = __float_as_uint(row[i]);
        keys[i] = (u & 0x80000000u) ? ~u : (u | 0x80000000u);  // monotone float->uint
    }
    __syncthreads();

    unsigned int prefix = 0; int k = 128;
    for (int sh = 24; sh >= 0; sh -= 8) {
        hist[tid] = 0;
        __syncthreads();
        unsigned int hmask = (sh == 24) ? 0u : (0xFFFFFFFFu << (sh + 8));
        for (int i = tid; i < T; i += 256) {
            unsigned int kk = keys[i];
            if ((kk & hmask) == prefix) atomicAdd(&hist[(kk >> sh) & 255], 1u);
        }
        __syncthreads();
        if (tid == 0) {
            int cum = 0;
            for (int bkt = 255; bkt >= 0; bkt--) {
                cum += (int)hist[bkt];
                if (cum >= k) {
                    sh_pref = prefix | ((unsigned int)bkt << sh);
                    sh_k = k - (cum - (int)hist[bkt]);
                    break;
                }
            }
        }
        __syncthreads();
        prefix = sh_pref; k = sh_k;
        __syncthreads();
    }
    unsigned int Tkey = prefix;
    int k_rem = k;
    int count_gt = 128 - k_rem;

    if (tid == 0) { gtc = 0; eqbase = 0; }
    __syncthreads();

    for (int i = tid; i < T; i += 256) {
        if (keys[i] > Tkey) {
            int p = atomicAdd(&gtc, 1);
            outbuf[p] = i;
        }
    }
    __syncthreads();

    for (int ch = 0; ch < T; ch += 256) {
        int i = ch + tid;
        bool eq = (keys[i] == Tkey);
        unsigned int bal = __ballot_sync(0xffffffffu, eq);
        int wpre = __popc(bal & ((1u << lane) - 1u));
        if (lane == 0) warpTot[wid] = __popc(bal);
        __syncthreads();
        int base = eqbase;
        int woff = 0;
        for (int w = 0; w < wid; w++) woff += warpTot[w];
        if (eq) {
            int rank = base + woff + wpre;
            if (rank < k_rem) outbuf[count_gt + rank] = i;
        }
        __syncthreads();
        if (tid == 0) {
            int tot = 0;
            for (int w = 0; w < 8; w++) tot += warpTot[w];
            eqbase += tot;
        }
        __syncthreads();
        if (eqbase >= k_rem) break;
    }

    for (int size = 2; size <= 128; size <<= 1) {
        for (int stride = size >> 1; stride > 0; stride >>= 1) {
            __syncthreads();
            if (tid < 128) {
                int partner = tid ^ stride;
                if (partner > tid) {
                    bool up = ((tid & size) == 0);
                    int a = outbuf[tid], b2 = outbuf[partner];
                    if ((a > b2) == up) { outbuf[tid] = b2; outbuf[partner] = a; }
                }
            }
        }
    }
    __syncthreads();
    if (tid < 128) g_indices[(size_t)bh*T + c*W + tid] = outbuf[tid];
}

// ---------------- K7: windowed attention + scatter (4-row register blocking) ----------------
#define ATTN_SMEM ((128*64 + 128*66 + 128*64 + 128*66) * 4 + 128 * 4)

__global__ __launch_bounds__(256, 1)
void k_attn(const float* __restrict__ qk, const float* __restrict__ v,
            const float* __restrict__ rw, float* __restrict__ out) {
    extern __shared__ float sm[];
    float* sQ = sm;                      // [128][64]
    float* sK = sQ + 128*64;             // [128][66]
    float* sV = sK + 128*66;             // [128][64]
    float* sR = sV + 128*64;             // [128][66]
    int*   sIdx = (int*)(sR + 128*66);

    int inst = blockIdx.x;
    int bh = inst / NC;
    int n  = inst % NC;
    int h  = bh % H;
    int tid = threadIdx.x, lane = tid & 31, wid = tid >> 5;

    if (tid < 128) sIdx[tid] = g_indices[(size_t)bh*T + n*W + tid];
    __syncthreads();

    for (int r = wid; r < 128; r += 8) {
        int g = sIdx[r];
        size_t off = ((size_t)bh*T + g) * D;
        float2 a = ((const float2*)(qk + off))[lane];
        float2 b2 = ((const float2*)(g_knorm + off))[lane];
        float2 c2 = ((const float2*)(v + off))[lane];
        sQ[r*64 + 2*lane] = a.x;  sQ[r*64 + 2*lane + 1] = a.y;
        sK[r*66 + 2*lane] = b2.x; sK[r*66 + 2*lane + 1] = b2.y;
        sV[r*64 + 2*lane] = c2.x; sV[r*64 + 2*lane + 1] = c2.y;
        float2 rr = ((const float2*)(rw + ((size_t)r*H + h)*D))[lane];
        sR[r*66 + 2*lane] = rr.x; sR[r*66 + 2*lane + 1] = rr.y;
    }
    __syncthreads();

    const float scale = 0.125f;

    for (int p = 0; p < 4; p++) {
        int irow[4];
        #pragma unroll
        for (int q = 0; q < 4; q++) irow[q] = wid + 8*q + 32*p;

        float a[4][4];
        #pragma unroll
        for (int q = 0; q < 4; q++)
            #pragma unroll
            for (int jj = 0; jj < 4; jj++) a[q][jj] = 0.f;

        #pragma unroll 4
        for (int d2 = 0; d2 < 32; d2++) {
            float2 qv[4];
            #pragma unroll
            for (int q = 0; q < 4; q++) qv[q] = *(const float2*)&sQ[irow[q]*64 + 2*d2];
            #pragma unroll
            for (int jj = 0; jj < 4; jj++) {
                float2 kv = *(const float2*)&sK[(lane + 32*jj)*66 + 2*d2];
                #pragma unroll
                for (int q = 0; q < 4; q++)
                    a[q][jj] += qv[q].x*kv.x + qv[q].y*kv.y;
            }
        }

        #pragma unroll
        for (int q = 0; q < 4; q++) {
            int i = irow[q];
            #pragma unroll
            for (int jj = 0; jj < 4; jj++) {
                int j = lane + 32*jj;
                if (j < i) {
                    int r = 127 + j - i;
                    float s = 0.f;
                    for (int d2 = 0; d2 < 32; d2++) {
                        float2 qq = *(const float2*)&sQ[i*64 + 2*d2];
                        float2 rr = *(const float2*)&sR[r*66 + 2*d2];
                        s += qq.x*rr.x + qq.y*rr.y;
                    }
                    a[q][jj] += s;
                }
            }
        }

        float pr[4][4];
        #pragma unroll
        for (int q = 0; q < 4; q++) {
            int i = irow[q];
            float m = -1e30f;
            #pragma unroll
            for (int jj = 0; jj < 4; jj++) {
                int j = lane + 32*jj;
                a[q][jj] = (j == i) ? -50000.0f : a[q][jj]*scale;
                m = fmaxf(m, a[q][jj]);
            }
            #pragma unroll
            for (int o = 16; o; o >>= 1) m = fmaxf(m, __shfl_xor_sync(0xffffffffu, m, o));
            float s = 0.f;
            #pragma unroll
            for (int jj = 0; jj < 4; jj++) { pr[q][jj] = expf(a[q][jj] - m); s += pr[q][jj]; }
            #pragma unroll
            for (int o = 16; o; o >>= 1) s += __shfl_xor_sync(0xffffffffu, s, o);
            float inv = 1.0f / s;
            #pragma unroll
            for (int jj = 0; jj < 4; jj++) pr[q][jj] *= inv;
        }

        float ox[4], oy[4];
        #pragma unroll
        for (int q = 0; q < 4; q++) { ox[q] = 0.f; oy[q] = 0.f; }
        #pragma unroll
        for (int jj = 0; jj < 4; jj++) {
            for (int js = 0; js < 32; js++) {
                float2 vv = ((const float2*)(sV + (jj*32 + js)*64))[lane];
                #pragma unroll
                for (int q = 0; q < 4; q++) {
                    float w = __shfl_sync(0xffffffffu, pr[q][jj], js);
                    ox[q] += w * vv.x;
                    oy[q] += w * vv.y;
                }
            }
        }

        #pragma unroll
        for (int q = 0; q < 4; q++) {
            int g = sIdx[irow[q]];
            float* dst = out + ((size_t)bh*T + g)*D + 2*lane;
            atomicAdd(dst,     ox[q]);
            atomicAdd(dst + 1, oy[q]);
            if (lane == 0) atomicAdd(&g_count[(size_t)bh*T + g], 1);
        }
    }
}

// ---------------- K8: finalize out /= (count + 1e-5) ----------------
__global__ void k_final(float* __restrict__ out) {
    size_t i = (size_t)blockIdx.x * blockDim.x + threadIdx.x;
    size_t stride = (size_t)gridDim.x * blockDim.x;
    const size_t N = (size_t)B*H*T*D;
    for (size_t p = i; p < N; p += stride) {
        float cnt = (float)g_count[p >> 6];
        out[p] = out[p] / (cnt + 1e-5f);
    }
}

// ---------------- launch ----------------
extern "C" void kernel_launch(void* const* d_in, const int* in_sizes, int n_in,
                              void* d_out, int out_size) {
    const float* qk    = (const float*)d_in[0];
    const float* v     = (const float*)d_in[1];
    const float* means = (const float*)d_in[2];
    const float* rw    = (const float*)d_in[3];
    float* out = (float*)d_out;

    cudaFuncSetAttribute(k_attn, cudaFuncAttributeMaxDynamicSharedMemorySize, ATTN_SMEM);

    k_zero<<<2048, 256>>>(out);
    k_norm<<<(B*H*T + 255)/256, 256>>>(qk);
    k_buckets<<<BH*(T/64), 256>>>(means);
    k_sumsC<<<BH*2, 1024>>>();
    k_meansupd<<<(H*C + 255)/256, 256>>>(means);
    k_dists<<<BH*(T/64), 256>>>();
    k_topk<<<BH*C, 256>>>();
    k_attn<<<BH*NC, 256, ATTN_SMEM>>>(qk, v, rw, out);
    k_final<<<4096, 256>>>(out);
}

// round 12
// speedup vs baseline: 1.4522x; 1.0382x over previous
#include <cuda_runtime.h>
#include <math.h>

#define B 4
#define H 16
#define T 8192
#define D 64
#define C 64
#define W 128
#define NC 64
#define BH (B*H)

// ---------------- scratch (static device globals; no runtime alloc) ----------------
__device__ float g_knorm[(size_t)B*H*T*D];   // 134 MB
__device__ float g_dists[(size_t)B*H*C*T];   // 134 MB, layout (b,h,c,t)
__device__ unsigned char g_bucketsB[B*H*T];
__device__ float g_part[(size_t)B*H*C*D];    // per-b partial sums, layout ((b,h,c),d)
__device__ int   g_bins[H*C];
__device__ float g_meansu[H*C*D];
__device__ int   g_indices[B*H*T];
__device__ int   g_count[B*H*T];

// Correctly-rounded division via Markstein sequence.
// r must be __frcp_rn(n) (correctly-rounded reciprocal). Result == __fdiv_rn(x,n)
// for all normal-range operands (no over/underflow in intermediates).
__device__ __forceinline__ float fdiv_rn_m(float x, float n, float r) {
    float q = __fmul_rn(x, r);
    float e = __fmaf_rn(-q, n, x);
    return __fmaf_rn(e, r, q);
}

// ---------------- K0: zero accumulators ----------------
__global__ void k_zero(float* __restrict__ out) {
    size_t i = (size_t)blockIdx.x * blockDim.x + threadIdx.x;
    size_t stride = (size_t)gridDim.x * blockDim.x;
    const size_t NOUT = (size_t)B*H*T*D;
    for (size_t p = i; p < NOUT; p += stride) out[p] = 0.f;
    for (size_t p = i; p < (size_t)B*H*T; p += stride) g_count[p] = 0;
    for (size_t p = i; p < (size_t)H*C; p += stride) g_bins[p] = 0;
}

// ---------------- K1: k_norm = l2norm(qk), bit-exact (sequential fused fma ssq; Markstein div) ----------------
__global__ void k_norm(const float* __restrict__ qk) {
    int tok = blockIdx.x * blockDim.x + threadIdx.x;
    if (tok >= B*H*T) return;
    const float4* src = (const float4*)(qk + (size_t)tok * D);
    float v[64];
    #pragma unroll
    for (int i = 0; i < 16; i++) {
        float4 q = src[i];
        v[4*i+0] = q.x; v[4*i+1] = q.y; v[4*i+2] = q.z; v[4*i+3] = q.w;
    }
    float s = 0.f;
    #pragma unroll
    for (int d = 0; d < 64; d++) s = __fmaf_rn(v[d], v[d], s);
    float n = fmaxf(__fsqrt_rn(s), 1e-12f);
    float r = __frcp_rn(n);
    float4* dst = (float4*)(g_knorm + (size_t)tok * D);
    #pragma unroll
    for (int i = 0; i < 16; i++) {
        float4 o;
        o.x = fdiv_rn_m(v[4*i+0], n, r);
        o.y = fdiv_rn_m(v[4*i+1], n, r);
        o.z = fdiv_rn_m(v[4*i+2], n, r);
        o.w = fdiv_rn_m(v[4*i+3], n, r);
        dst[i] = o;
    }
}

// ---------------- K2: buckets = argmax_c (k_norm . means) ----------------
__global__ void k_buckets(const float* __restrict__ means) {
    __shared__ float sM[64*68];   // [d][c]
    __shared__ float sT[64*68];   // [d][tok]
    int blk = blockIdx.x;
    int bh = blk / (T/64);
    int chunk = blk % (T/64);
    int h = bh % H;
    int tid = threadIdx.x;

    for (int i = tid; i < C*D; i += 256) {
        int c = i >> 6, d = i & 63;
        sM[d*68 + c] = means[(size_t)h*C*D + i];
    }
    size_t base = ((size_t)bh*T + (size_t)chunk*64) * D;
    for (int i = tid; i < 64*D; i += 256) {
        int r = i >> 6, d = i & 63;
        sT[d*68 + r] = g_knorm[base + i];
    }
    __syncthreads();

    int tx = tid & 15, ty = tid >> 4;
    int tok0 = ty*4, c0 = tx*4;
    float a[4][4];
    #pragma unroll
    for (int r = 0; r < 4; r++)
        #pragma unroll
        for (int cc = 0; cc < 4; cc++) a[r][cc] = 0.f;

    #pragma unroll 8
    for (int d = 0; d < 64; d++) {
        float4 q4 = *(const float4*)&sT[d*68 + tok0];
        float4 m4 = *(const float4*)&sM[d*68 + c0];
        float qv[4] = {q4.x, q4.y, q4.z, q4.w};
        float mv[4] = {m4.x, m4.y, m4.z, m4.w};
        #pragma unroll
        for (int r = 0; r < 4; r++)
            #pragma unroll
            for (int cc = 0; cc < 4; cc++)
                a[r][cc] = __fmaf_rn(qv[r], mv[cc], a[r][cc]);
    }
    __syncthreads();

    float* sSim = sM;
    #pragma unroll
    for (int r = 0; r < 4; r++)
        #pragma unroll
        for (int cc = 0; cc < 4; cc++)
            sSim[(tok0 + r)*64 + c0 + cc] = a[r][cc];
    __syncthreads();

    if (tid < 64) {
        float best = -1e30f; int bi = 0;
        #pragma unroll 8
        for (int c = 0; c < C; c++) {
            float s = sSim[tid*64 + c];
            if (s > best) { best = s; bi = c; }   // strict > : first index on ties
        }
        g_bucketsB[(size_t)bh*T + chunk*64 + tid] = (unsigned char)bi;
    }
}

// ---------------- K3: cluster sums — byte-packed smem buckets, vcmpeq4 scan ----------------
// 2 blocks x 1024 threads per (b,h); warp w owns cluster c = half*32 + wid.
// 16 tokens per LDS.128; per-cluster additions in strict ascending-t order.
__global__ __launch_bounds__(1024, 1) void k_sumsC() {
    __shared__ unsigned int sb[T/4];      // 8 KB (byte buckets)
    int bh = blockIdx.x >> 1;
    int half = blockIdx.x & 1;
    int tid = threadIdx.x;
    int lane = tid & 31, wid = tid >> 5;
    size_t base = (size_t)bh * T;
    for (int i = tid; i < T/16; i += 1024)
        ((uint4*)sb)[i] = ((const uint4*)(g_bucketsB + base))[i];
    __syncthreads();

    int c = half*32 + wid;
    unsigned int cc = (unsigned int)c * 0x01010101u;
    float ax = 0.f, ay = 0.f;
    int cnt = 0;

    #define ADDTOK(tt) { float2 xv = ((const float2*)(g_knorm + (base + (tt))*D))[lane]; \
                         ax = __fadd_rn(ax, xv.x); ay = __fadd_rn(ay, xv.y); cnt++; }
    #define SCANW(u, t0) { unsigned int m = __vcmpeq4((u), cc); \
        if (m) { if (m & 0x000000FFu) ADDTOK((t0)+0); if (m & 0x0000FF00u) ADDTOK((t0)+1); \
                 if (m & 0x00FF0000u) ADDTOK((t0)+2); if (m & 0xFF000000u) ADDTOK((t0)+3); } }

    for (int t = 0; t < T; t += 16) {
        uint4 w = *(const uint4*)&sb[t >> 2];
        SCANW(w.x, t+0);
        SCANW(w.y, t+4);
        SCANW(w.z, t+8);
        SCANW(w.w, t+12);
    }
    #undef SCANW
    #undef ADDTOK

    float2 o; o.x = ax; o.y = ay;
    ((float2*)(g_part + ((size_t)bh*C + c) * D))[lane] = o;
    if (lane == 0) atomicAdd(&g_bins[(bh & (H-1))*C + c], cnt);
}

// ---------------- K4: means_upd: b-ascending combine + fused sequential ssq + Markstein div ----------------
__global__ void k_meansupd(const float* __restrict__ means) {
    int inst = blockIdx.x * blockDim.x + threadIdx.x;   // h*C + c
    if (inst >= H*C) return;
    float sv[64];
    #pragma unroll 4
    for (int d = 0; d < D; d++) {
        float s = g_part[((size_t)0*1024 + inst)*D + d];
        s = __fadd_rn(s, g_part[((size_t)1*1024 + inst)*D + d]);
        s = __fadd_rn(s, g_part[((size_t)2*1024 + inst)*D + d]);
        s = __fadd_rn(s, g_part[((size_t)3*1024 + inst)*D + d]);
        sv[d] = s;
    }
    float ssq = 0.f;
    #pragma unroll
    for (int d = 0; d < D; d++) ssq = __fmaf_rn(sv[d], sv[d], ssq);
    float n = fmaxf(__fsqrt_rn(ssq), 1e-12f);
    float r = __frcp_rn(n);
    bool empty = (g_bins[inst] == 0);
    #pragma unroll 4
    for (int d = 0; d < D; d++) {
        float o = empty ? means[(size_t)inst*D + d] : fdiv_rn_m(sv[d], n, r);
        g_meansu[(size_t)inst*D + d] = o;
    }
}

// ---------------- K5: dists (b,h,c,t) = k_norm . means_upd^T ----------------
__global__ void k_dists() {
    __shared__ float sM[64*68];
    __shared__ float sT[64*68];
    int blk = blockIdx.x;
    int bh = blk / (T/64);
    int chunk = blk % (T/64);
    int h = bh % H;
    int tid = threadIdx.x;

    for (int i = tid; i < C*D; i += 256) {
        int c = i >> 6, d = i & 63;
        sM[d*68 + c] = g_meansu[(size_t)h*C*D + i];
    }
    size_t base = ((size_t)bh*T + (size_t)chunk*64) * D;
    for (int i = tid; i < 64*D; i += 256) {
        int r = i >> 6, d = i & 63;
        sT[d*68 + r] = g_knorm[base + i];
    }
    __syncthreads();

    int tx = tid & 15, ty = tid >> 4;
    int tok0 = ty*4, c0 = tx*4;
    float a[4][4];
    #pragma unroll
    for (int r = 0; r < 4; r++)
        #pragma unroll
        for (int cc = 0; cc < 4; cc++) a[r][cc] = 0.f;

    #pragma unroll 8
    for (int d = 0; d < 64; d++) {
        float4 q4 = *(const float4*)&sT[d*68 + tok0];
        float4 m4 = *(const float4*)&sM[d*68 + c0];
        float qv[4] = {q4.x, q4.y, q4.z, q4.w};
        float mv[4] = {m4.x, m4.y, m4.z, m4.w};
        #pragma unroll
        for (int r = 0; r < 4; r++)
            #pragma unroll
            for (int cc = 0; cc < 4; cc++)
                a[r][cc] = __fmaf_rn(qv[r], mv[cc], a[r][cc]);
    }
    __syncthreads();

    float* sSim = sM;    // alias: [c][tok] for coalesced store
    #pragma unroll
    for (int r = 0; r < 4; r++)
        #pragma unroll
        for (int cc = 0; cc < 4; cc++)
            sSim[(c0 + cc)*64 + tok0 + r] = a[r][cc];
    __syncthreads();

    for (int i = tid; i < C*64; i += 256) {
        int c = i >> 6, t = i & 63;
        g_dists[((size_t)bh*C + c)*T + (size_t)chunk*64 + t] = sSim[i];
    }
}

// ---------------- K6: top-128 per (b,h,c): radix select + bitonic index sort ----------------
__global__ void k_topk() {
    __shared__ unsigned int keys[T];        // 32 KB
    __shared__ unsigned int hist[256];
    __shared__ unsigned int sh_pref;
    __shared__ int sh_k;
    __shared__ int outbuf[W];
    __shared__ int gtc;
    __shared__ int eqbase;
    __shared__ int warpTot[8];

    int inst = blockIdx.x;                  // (b*H+h)*C + c
    int bh = inst / C;
    int c = inst % C;
    int tid = threadIdx.x, lane = tid & 31, wid = tid >> 5;

    const float* row = g_dists + (size_t)inst * T;
    for (int i = tid; i < T; i += 256) {
        unsigned int u = __float_as_uint(row[i]);
        keys[i] = (u & 0x80000000u) ? ~u : (u | 0x80000000u);  // monotone float->uint
    }
    __syncthreads();

    unsigned int prefix = 0; int k = 128;
    for (int sh = 24; sh >= 0; sh -= 8) {
        hist[tid] = 0;
        __syncthreads();
        unsigned int hmask = (sh == 24) ? 0u : (0xFFFFFFFFu << (sh + 8));
        for (int i = tid; i < T; i += 256) {
            unsigned int kk = keys[i];
            if ((kk & hmask) == prefix) atomicAdd(&hist[(kk >> sh) & 255], 1u);
        }
        __syncthreads();
        if (tid == 0) {
            int cum = 0;
            for (int bkt = 255; bkt >= 0; bkt--) {
                cum += (int)hist[bkt];
                if (cum >= k) {
                    sh_pref = prefix | ((unsigned int)bkt << sh);
                    sh_k = k - (cum - (int)hist[bkt]);
                    break;
                }
            }
        }
        __syncthreads();
        prefix = sh_pref; k = sh_k;
        __syncthreads();
    }
    unsigned int Tkey = prefix;
    int k_rem = k;
    int count_gt = 128 - k_rem;

    if (tid == 0) { gtc = 0; eqbase = 0; }
    __syncthreads();

    for (int i = tid; i < T; i += 256) {
        if (keys[i] > Tkey) {
            int p = atomicAdd(&gtc, 1);
            outbuf[p] = i;
        }
    }
    __syncthreads();

    for (int ch = 0; ch < T; ch += 256) {
        int i = ch + tid;
        bool eq = (keys[i] == Tkey);
        unsigned int bal = __ballot_sync(0xffffffffu, eq);
        int wpre = __popc(bal & ((1u << lane) - 1u));
        if (lane == 0) warpTot[wid] = __popc(bal);
        __syncthreads();
        int base = eqbase;
        int woff = 0;
        for (int w = 0; w < wid; w++) woff += warpTot[w];
        if (eq) {
            int rank = base + woff + wpre;
            if (rank < k_rem) outbuf[count_gt + rank] = i;
        }
        __syncthreads();
        if (tid == 0) {
            int tot = 0;
            for (int w = 0; w < 8; w++) tot += warpTot[w];
            eqbase += tot;
        }
        __syncthreads();
        if (eqbase >= k_rem) break;
    }

    for (int size = 2; size <= 128; size <<= 1) {
        for (int stride = size >> 1; stride > 0; stride >>= 1) {
            __syncthreads();
            if (tid < 128) {
                int partner = tid ^ stride;
                if (partner > tid) {
                    bool up = ((tid & size) == 0);
                    int a = outbuf[tid], b2 = outbuf[partner];
                    if ((a > b2) == up) { outbuf[tid] = b2; outbuf[partner] = a; }
                }
            }
        }
    }
    __syncthreads();
    if (tid < 128) g_indices[(size_t)bh*T + c*W + tid] = outbuf[tid];
}

// ---------------- K7: windowed attention + scatter (4-row register blocking) ----------------
#define ATTN_SMEM ((128*64 + 128*66 + 128*64 + 128*66) * 4 + 128 * 4)

__global__ __launch_bounds__(256, 1)
void k_attn(const float* __restrict__ qk, const float* __restrict__ v,
            const float* __restrict__ rw, float* __restrict__ out) {
    extern __shared__ float sm[];
    float* sQ = sm;                      // [128][64]
    float* sK = sQ + 128*64;             // [128][66]
    float* sV = sK + 128*66;             // [128][64]
    float* sR = sV + 128*64;             // [128][66]
    int*   sIdx = (int*)(sR + 128*66);

    int inst = blockIdx.x;
    int bh = inst / NC;
    int n  = inst % NC;
    int h  = bh % H;
    int tid = threadIdx.x, lane = tid & 31, wid = tid >> 5;

    if (tid < 128) sIdx[tid] = g_indices[(size_t)bh*T + n*W + tid];
    __syncthreads();

    for (int r = wid; r < 128; r += 8) {
        int g = sIdx[r];
        size_t off = ((size_t)bh*T + g) * D;
        float2 a = ((const float2*)(qk + off))[lane];
        float2 b2 = ((const float2*)(g_knorm + off))[lane];
        float2 c2 = ((const float2*)(v + off))[lane];
        sQ[r*64 + 2*lane] = a.x;  sQ[r*64 + 2*lane + 1] = a.y;
        sK[r*66 + 2*lane] = b2.x; sK[r*66 + 2*lane + 1] = b2.y;
        sV[r*64 + 2*lane] = c2.x; sV[r*64 + 2*lane + 1] = c2.y;
        float2 rr = ((const float2*)(rw + ((size_t)r*H + h)*D))[lane];
        sR[r*66 + 2*lane] = rr.x; sR[r*66 + 2*lane + 1] = rr.y;
    }
    __syncthreads();

    const float scale = 0.125f;

    for (int p = 0; p < 4; p++) {
        int irow[4];
        #pragma unroll
        for (int q = 0; q < 4; q++) irow[q] = wid + 8*q + 32*p;

        float a[4][4];
        #pragma unroll
        for (int q = 0; q < 4; q++)
            #pragma unroll
            for (int jj = 0; jj < 4; jj++) a[q][jj] = 0.f;

        #pragma unroll 4
        for (int d2 = 0; d2 < 32; d2++) {
            float2 qv[4];
            #pragma unroll
            for (int q = 0; q < 4; q++) qv[q] = *(const float2*)&sQ[irow[q]*64 + 2*d2];
            #pragma unroll
            for (int jj = 0; jj < 4; jj++) {
                float2 kv = *(const float2*)&sK[(lane + 32*jj)*66 + 2*d2];
                #pragma unroll
                for (int q = 0; q < 4; q++)
                    a[q][jj] += qv[q].x*kv.x + qv[q].y*kv.y;
            }
        }

        #pragma unroll
        for (int q = 0; q < 4; q++) {
            int i = irow[q];
            #pragma unroll
            for (int jj = 0; jj < 4; jj++) {
                int j = lane + 32*jj;
                if (j < i) {
                    int r = 127 + j - i;
                    float s = 0.f;
                    for (int d2 = 0; d2 < 32; d2++) {
                        float2 qq = *(const float2*)&sQ[i*64 + 2*d2];
                        float2 rr = *(const float2*)&sR[r*66 + 2*d2];
                        s += qq.x*rr.x + qq.y*rr.y;
                    }
                    a[q][jj] += s;
                }
            }
        }

        float pr[4][4];
        #pragma unroll
        for (int q = 0; q < 4; q++) {
            int i = irow[q];
            float m = -1e30f;
            #pragma unroll
            for (int jj = 0; jj < 4; jj++) {
                int j = lane + 32*jj;
                a[q][jj] = (j == i) ? -50000.0f : a[q][jj]*scale;
                m = fmaxf(m, a[q][jj]);
            }
            #pragma unroll
            for (int o = 16; o; o >>= 1) m = fmaxf(m, __shfl_xor_sync(0xffffffffu, m, o));
            float s = 0.f;
            #pragma unroll
            for (int jj = 0; jj < 4; jj++) { pr[q][jj] = __expf(a[q][jj] - m); s += pr[q][jj]; }
            #pragma unroll
            for (int o = 16; o; o >>= 1) s += __shfl_xor_sync(0xffffffffu, s, o);
            float inv = __frcp_rn(s);
            #pragma unroll
            for (int jj = 0; jj < 4; jj++) pr[q][jj] *= inv;
        }

        float ox[4], oy[4];
        #pragma unroll
        for (int q = 0; q < 4; q++) { ox[q] = 0.f; oy[q] = 0.f; }
        #pragma unroll
        for (int jj = 0; jj < 4; jj++) {
            for (int js = 0; js < 32; js++) {
                float2 vv = ((const float2*)(sV + (jj*32 + js)*64))[lane];
                #pragma unroll
                for (int q = 0; q < 4; q++) {
                    float w = __shfl_sync(0xffffffffu, pr[q][jj], js);
                    ox[q] += w * vv.x;
                    oy[q] += w * vv.y;
                }
            }
        }

        #pragma unroll
        for (int q = 0; q < 4; q++) {
            int g = sIdx[irow[q]];
            float* dst = out + ((size_t)bh*T + g)*D + 2*lane;
            atomicAdd(dst,     ox[q]);
            atomicAdd(dst + 1, oy[q]);
            if (lane == 0) atomicAdd(&g_count[(size_t)bh*T + g], 1);
        }
    }
}

// ---------------- K8: finalize out /= (count + 1e-5), warp per token, Markstein ----------------
__global__ void k_final(float* __restrict__ out) {
    int tok = blockIdx.x * (blockDim.x >> 5) + (threadIdx.x >> 5);
    int lane = threadIdx.x & 31;
    if (tok >= B*H*T) return;
    float dnm = (float)g_count[tok] + 1e-5f;
    float r = __frcp_rn(dnm);
    float2* p = (float2*)(out + (size_t)tok * D);
    float2 val = p[lane];
    val.x = fdiv_rn_m(val.x, dnm, r);
    val.y = fdiv_rn_m(val.y, dnm, r);
    p[lane] = val;
}

// ---------------- launch ----------------
extern "C" void kernel_launch(void* const* d_in, const int* in_sizes, int n_in,
                              void* d_out, int out_size) {
    const float* qk    = (const float*)d_in[0];
    const float* v     = (const float*)d_in[1];
    const float* means = (const float*)d_in[2];
    const float* rw    = (const float*)d_in[3];
    float* out = (float*)d_out;

    cudaFuncSetAttribute(k_attn, cudaFuncAttributeMaxDynamicSharedMemorySize, ATTN_SMEM);

    k_zero<<<2048, 256>>>(out);
    k_norm<<<(B*H*T + 255)/256, 256>>>(qk);
    k_buckets<<<BH*(T/64), 256>>>(means);
    k_sumsC<<<BH*2, 1024>>>();
    k_meansupd<<<(H*C + 255)/256, 256>>>(means);
    k_dists<<<BH*(T/64), 256>>>();
    k_topk<<<BH*C, 256>>>();
    k_attn<<<BH*NC, 256, ATTN_SMEM>>>(qk, v, rw, out);
    k_final<<<(B*H*T)/8, 256>>>(out);
}